// round 15
// baseline (speedup 1.0000x reference)
#include <cuda_runtime.h>
#include <cuda_fp16.h>
#include <cstdint>
#include <mma.h>
#include <math.h>

using namespace nvcuda;

#define N_CELLS 512
#define N_GENES 256
#define D 128
#define HEADS 4
#define HD 32
#define E_SP 8192
#define E_GRN 2048

#define PAD_A 132
#define PAD_B 136
#define PAD_H 136

// ---------------- scratch ----------------
__device__ float g_agg[N_CELLS * D];
__device__ float g_hid[N_CELLS * 256];
__device__ float g_high_out[N_CELLS * D];
__device__ float g_q[N_CELLS * N_GENES * D];
__device__ float g_k[N_CELLS * N_GENES * D];
__device__ float g_v[N_CELLS * N_GENES * D];
__device__ float g_skip[N_CELLS * N_GENES * D];
__device__ float g_attn[N_CELLS * N_GENES * D];
__device__ float g_low_out[N_CELLS * N_GENES * D];
__device__ float g_gene_agg[N_CELLS * D];
__device__ float g_low_cross[N_CELLS * D];
__device__ float g_cross6[6 * N_CELLS * D];
__device__ int g_off[N_GENES + 1];
__device__ int g_edge[E_GRN];

// ---------------- helpers ----------------
__device__ __forceinline__ float geluf(float x) {
    return 0.5f * x * (1.f + erff(x * 0.7071067811865476f));
}
__device__ __forceinline__ float sigmoidf_(float x) {
    return 1.f / (1.f + expf(-x));
}
__device__ __forceinline__ float warpSum(float v) {
#pragma unroll
    for (int o = 16; o; o >>= 1) v += __shfl_xor_sync(0xffffffffu, v, o);
    return v;
}
__device__ __forceinline__ void cp16(void* smem, const void* g) {
    unsigned s = (unsigned)__cvta_generic_to_shared(smem);
    asm volatile("cp.async.cg.shared.global [%0], [%1], 16;\n" :: "r"(s), "l"(g));
}
#define CP_COMMIT() asm volatile("cp.async.commit_group;\n" ::: "memory")
#define CP_WAIT0()  asm volatile("cp.async.wait_group 0;\n" ::: "memory")

typedef wmma::fragment<wmma::matrix_a, 16, 16, 8, wmma::precision::tf32, wmma::row_major> FragA;
typedef wmma::fragment<wmma::matrix_b, 16, 16, 8, wmma::precision::tf32, wmma::row_major> FragB;
typedef wmma::fragment<wmma::accumulator, 16, 16, 8, float> FragC;
typedef wmma::fragment<wmma::matrix_a, 16, 16, 16, __half, wmma::row_major> FragAH;
typedef wmma::fragment<wmma::matrix_b, 16, 16, 16, __half, wmma::row_major> FragBH;
typedef wmma::fragment<wmma::accumulator, 16, 16, 16, float> FragCH;

// ---------------- K0: zero spatial agg ----------------
__global__ void k_zero() {
    int i = blockIdx.x * blockDim.x + threadIdx.x;
    if (i < N_CELLS * D) g_agg[i] = 0.f;
}

// ---------------- K1: spatial scatter-add ----------------
__global__ void k_scatter(const float* __restrict__ high, const int* __restrict__ sp) {
    int idx = blockIdx.x * blockDim.x + threadIdx.x;
    if (idx >= E_SP * D) return;
    int e = idx >> 7, d = idx & 127;
    int s = sp[e];
    int t = sp[E_SP + e];
    atomicAdd(&g_agg[t * D + d], high[s * D + d]);
}

// ---------------- K2: build CSR over grn edges (packed src|dst) -------
__global__ void k_csr(const int* __restrict__ grn) {
    __shared__ int cnt[N_GENES];
    __shared__ int cur[N_GENES];
    int tid = threadIdx.x;
    if (tid < N_GENES) cnt[tid] = 0;
    __syncthreads();
    for (int e = tid; e < E_GRN; e += blockDim.x) atomicAdd(&cnt[grn[E_GRN + e]], 1);
    __syncthreads();
    if (tid == 0) {
        int run = 0;
        for (int g = 0; g < N_GENES; ++g) {
            g_off[g] = run;
            cur[g] = run;
            run += cnt[g];
        }
        g_off[N_GENES] = run;
    }
    __syncthreads();
    for (int e = tid; e < E_GRN; e += blockDim.x) {
        int dg = grn[E_GRN + e];
        int p = atomicAdd(&cur[dg], 1);
        g_edge[p] = grn[e] | (dg << 16);
    }
}

// ---------------- K3a: GIN layer-1 GEMM + gelu ----------------
__global__ void __launch_bounds__(256) k_gin1(const float* __restrict__ high,
        const float* __restrict__ w1, const float* __restrict__ b1,
        const float* __restrict__ epsp) {
    extern __shared__ float sm[];
    float* As = sm;
    float* Bs = sm + 128 * PAD_A;
    int tid = threadIdx.x;
    int warp = tid >> 5;
    int wm = warp >> 1, wn = warp & 1;
    int row0 = blockIdx.x * 128;
    int n0 = blockIdx.y * 128;
    float ep = 1.f + epsp[0];

    for (int i = tid; i < 128 * 32; i += 256) {
        int k = i >> 5, ch = i & 31;
        cp16(Bs + k * PAD_B + ch * 4, w1 + k * 256 + n0 + ch * 4);
    }
    CP_COMMIT();
    for (int i = tid; i < 128 * 32; i += 256) {
        int r = i >> 5, ch = i & 31;
        float4 h4 = *(const float4*)(high + (row0 + r) * 128 + ch * 4);
        float4 a4 = *(const float4*)(g_agg + (row0 + r) * 128 + ch * 4);
        float* dst = As + r * PAD_A + ch * 4;
        dst[0] = fmaf(ep, h4.x, a4.x);
        dst[1] = fmaf(ep, h4.y, a4.y);
        dst[2] = fmaf(ep, h4.z, a4.z);
        dst[3] = fmaf(ep, h4.w, a4.w);
    }
    CP_WAIT0();
    __syncthreads();

    FragC acc[2][4];
#pragma unroll
    for (int i = 0; i < 2; i++)
#pragma unroll
        for (int j = 0; j < 4; j++) wmma::fill_fragment(acc[i][j], 0.f);
#pragma unroll
    for (int k0 = 0; k0 < 128; k0 += 8) {
        FragA a[2];
#pragma unroll
        for (int i = 0; i < 2; i++)
            wmma::load_matrix_sync(a[i], As + (wm * 32 + i * 16) * PAD_A + k0, PAD_A);
        FragB b[4];
#pragma unroll
        for (int j = 0; j < 4; j++)
            wmma::load_matrix_sync(b[j], Bs + k0 * PAD_B + wn * 64 + j * 16, PAD_B);
#pragma unroll
        for (int i = 0; i < 2; i++)
#pragma unroll
            for (int j = 0; j < 4; j++)
                wmma::mma_sync(acc[i][j], a[i], b[j], acc[i][j]);
    }
    __syncthreads();
#pragma unroll
    for (int i = 0; i < 2; i++)
#pragma unroll
        for (int j = 0; j < 4; j++)
            wmma::store_matrix_sync(As + (wm * 32 + i * 16) * PAD_A + wn * 64 + j * 16,
                                    acc[i][j], PAD_A, wmma::mem_row_major);
    __syncthreads();
    for (int i = tid; i < 128 * 128; i += 256) {
        int r = i >> 7, n = i & 127;
        g_hid[(row0 + r) * 256 + n0 + n] = geluf(As[r * PAD_A + n] + b1[n0 + n]);
    }
}

// ---------------- K3b: GIN layer-2 GEMM + LN ----------------
__global__ void __launch_bounds__(256) k_gin2(
        const float* __restrict__ w2, const float* __restrict__ b2,
        const float* __restrict__ lng, const float* __restrict__ lnb) {
    extern __shared__ float sm[];
    float* As = sm;
    float* Bs = sm + 128 * PAD_A;
    int tid = threadIdx.x;
    int warp = tid >> 5, lane = tid & 31;
    int wm = warp >> 1, wn = warp & 1;
    int row0 = blockIdx.x * 128;

    FragC acc[2][4];
#pragma unroll
    for (int i = 0; i < 2; i++)
#pragma unroll
        for (int j = 0; j < 4; j++) wmma::fill_fragment(acc[i][j], 0.f);

    for (int kc = 0; kc < 256; kc += 128) {
        for (int i = tid; i < 128 * 32; i += 256) {
            int r = i >> 5, ch = i & 31;
            cp16(As + r * PAD_A + ch * 4, g_hid + (row0 + r) * 256 + kc + ch * 4);
            cp16(Bs + r * PAD_B + ch * 4, w2 + (kc + r) * 128 + ch * 4);
        }
        CP_COMMIT();
        CP_WAIT0();
        __syncthreads();
#pragma unroll
        for (int k0 = 0; k0 < 128; k0 += 8) {
            FragA a[2];
#pragma unroll
            for (int i = 0; i < 2; i++)
                wmma::load_matrix_sync(a[i], As + (wm * 32 + i * 16) * PAD_A + k0, PAD_A);
            FragB b[4];
#pragma unroll
            for (int j = 0; j < 4; j++)
                wmma::load_matrix_sync(b[j], Bs + k0 * PAD_B + wn * 64 + j * 16, PAD_B);
#pragma unroll
            for (int i = 0; i < 2; i++)
#pragma unroll
                for (int j = 0; j < 4; j++)
                    wmma::mma_sync(acc[i][j], a[i], b[j], acc[i][j]);
        }
        __syncthreads();
    }
#pragma unroll
    for (int i = 0; i < 2; i++)
#pragma unroll
        for (int j = 0; j < 4; j++)
            wmma::store_matrix_sync(As + (wm * 32 + i * 16) * PAD_A + wn * 64 + j * 16,
                                    acc[i][j], PAD_A, wmma::mem_row_major);
    __syncthreads();
    float4 bb2 = *(const float4*)(b2 + lane * 4);
    float4 gg = *(const float4*)(lng + lane * 4);
    float4 bb = *(const float4*)(lnb + lane * 4);
    for (int r = warp; r < 128; r += 8) {
        float4 x = *(float4*)(As + r * PAD_A + lane * 4);
        x.x += bb2.x; x.y += bb2.y; x.z += bb2.z; x.w += bb2.w;
        float sum = warpSum(x.x + x.y + x.z + x.w);
        float sq = warpSum(x.x * x.x + x.y * x.y + x.z * x.z + x.w * x.w);
        float mean = sum * (1.f / D);
        float var = sq * (1.f / D) - mean * mean;
        float inv = rsqrtf(var + 1e-5f);
        float4 y;
        y.x = (x.x - mean) * inv * gg.x + bb.x;
        y.y = (x.y - mean) * inv * gg.y + bb.y;
        y.z = (x.z - mean) * inv * gg.z + bb.z;
        y.w = (x.w - mean) * inv * gg.w + bb.w;
        *(float4*)(g_high_out + (size_t)(row0 + r) * 128 + lane * 4) = y;
    }
}

// ---------------- K4: projection GEMM — fp16, full 128-col tile -------------
// grid (1024 row-tiles, 4 weights). smem ~70KB. Warp tile 32x64 (acc 2x4).
__global__ void __launch_bounds__(256) k_proj(const float* __restrict__ A,
        const float* __restrict__ wq, const float* __restrict__ wk,
        const float* __restrict__ wv, const float* __restrict__ ws) {
    extern __shared__ __half smh[];
    __half* As = smh;                     // [128][PAD_H]
    __half* Bs = smh + 128 * PAD_H;       // [128][PAD_H]
    int tid = threadIdx.x;
    int warp = tid >> 5;
    int wm = warp >> 1, wn = warp & 1;    // 4x2 warps; warp tile 32x64
    size_t row0 = (size_t)blockIdx.x * 128;
    int w = blockIdx.y;

    const float* Ws[4] = {wq, wk, wv, ws};
    float* Outs[4] = {g_q, g_k, g_v, g_skip};
    const float* B = Ws[w];

    for (int i = tid; i < 128 * 32; i += 256) {
        int r = i >> 5, ch = i & 31;
        float4 va = *(const float4*)(A + (row0 + r) * 128 + ch * 4);
        float4 vb = *(const float4*)(B + r * 128 + ch * 4);
        __half2* da = (__half2*)(As + r * PAD_H + ch * 4);
        __half2* db = (__half2*)(Bs + r * PAD_H + ch * 4);
        da[0] = __floats2half2_rn(va.x, va.y);
        da[1] = __floats2half2_rn(va.z, va.w);
        db[0] = __floats2half2_rn(vb.x, vb.y);
        db[1] = __floats2half2_rn(vb.z, vb.w);
    }
    __syncthreads();

    FragCH acc[2][4];
#pragma unroll
    for (int i = 0; i < 2; i++)
#pragma unroll
        for (int j = 0; j < 4; j++) wmma::fill_fragment(acc[i][j], 0.f);
#pragma unroll
    for (int k0 = 0; k0 < 128; k0 += 16) {
        FragAH a[2];
#pragma unroll
        for (int i = 0; i < 2; i++)
            wmma::load_matrix_sync(a[i], As + (wm * 32 + i * 16) * PAD_H + k0, PAD_H);
        FragBH b[4];
#pragma unroll
        for (int j = 0; j < 4; j++)
            wmma::load_matrix_sync(b[j], Bs + k0 * PAD_H + wn * 64 + j * 16, PAD_H);
#pragma unroll
        for (int i = 0; i < 2; i++)
#pragma unroll
            for (int j = 0; j < 4; j++)
                wmma::mma_sync(acc[i][j], a[i], b[j], acc[i][j]);
    }
    float* Out = Outs[w];
#pragma unroll
    for (int i = 0; i < 2; i++)
#pragma unroll
        for (int j = 0; j < 4; j++)
            wmma::store_matrix_sync(Out + (row0 + wm * 32 + i * 16) * 128 + wn * 64 + j * 16,
                                    acc[i][j], 128, wmma::mem_row_major);
}

// ---------------- K5: attention — head-split (512 cells, 2), ILP-2 Phase C --
__global__ void __launch_bounds__(512) k_attn(const float* __restrict__ bq,
                                              const float* __restrict__ bk,
                                              const float* __restrict__ bv) {
    extern __shared__ float sm[];
    float* qs = sm;
    float* kvs = qs + N_GENES * 33;
    float* alpha = kvs + N_GENES * 33;
    float* invd = alpha + E_GRN;
    int* sedge = (int*)(invd + N_GENES);
    int* soff = sedge + E_GRN;
    int c = blockIdx.x, tid = threadIdx.x;
    int lane = tid & 31, warp = tid >> 5;
    int h0 = blockIdx.y * 2;
    for (int i = tid; i < E_GRN; i += 512) sedge[i] = g_edge[i];
    for (int i = tid; i <= N_GENES; i += 512) soff[i] = g_off[i];
    const float* qb = g_q + (size_t)c * N_GENES * D;
    const float* kb = g_k + (size_t)c * N_GENES * D;
    const float* vb = g_v + (size_t)c * N_GENES * D;
    float* ob = g_attn + (size_t)c * N_GENES * D;
    int go0 = 0, go1 = 0;
    if (tid < N_GENES) { go0 = g_off[tid]; go1 = g_off[tid + 1]; }

    for (int h = h0; h < h0 + 2; ++h) {
        __syncthreads();
        int hb = h * HD;
        for (int i = tid; i < N_GENES * 8; i += 512) {
            int g = i >> 3, dq = (i & 7) * 4;
            float4 qv = *(const float4*)(qb + g * D + hb + dq);
            float4 kv = *(const float4*)(kb + g * D + hb + dq);
            float4 b1 = *(const float4*)(bq + hb + dq);
            float4 b2 = *(const float4*)(bk + hb + dq);
            float* qd = qs + g * 33 + dq;
            float* kd = kvs + g * 33 + dq;
            qd[0] = qv.x + b1.x; qd[1] = qv.y + b1.y; qd[2] = qv.z + b1.z; qd[3] = qv.w + b1.w;
            kd[0] = kv.x + b2.x; kd[1] = kv.y + b2.y; kd[2] = kv.z + b2.z; kd[3] = kv.w + b2.w;
        }
        __syncthreads();

        // Phase A: edge-parallel logits
        for (int e = tid; e < E_GRN; e += 512) {
            int pk = sedge[e];
            int s = pk & 0xffff, dg = pk >> 16;
            const float* qr = qs + dg * 33;
            const float* kr = kvs + s * 33;
            float t0 = 0.f, t1 = 0.f;
#pragma unroll
            for (int d = 0; d < HD; d += 2) {
                t0 = fmaf(qr[d], kr[d], t0);
                t1 = fmaf(qr[d + 1], kr[d + 1], t1);
            }
            alpha[e] = (t0 + t1) * 0.17677669529663689f;
        }
        __syncthreads();

        // Phase B: stage v+bv into kvs (k dead) + softmax (deferred normalize)
        for (int i = tid; i < N_GENES * 8; i += 512) {
            int g = i >> 3, dq = (i & 7) * 4;
            float4 vv = *(const float4*)(vb + g * D + hb + dq);
            float4 b3 = *(const float4*)(bv + hb + dq);
            float* vd = kvs + g * 33 + dq;
            vd[0] = vv.x + b3.x; vd[1] = vv.y + b3.y; vd[2] = vv.z + b3.z; vd[3] = vv.w + b3.w;
        }
        if (tid < N_GENES) {
            float inv = 0.f;
            if (go1 > go0) {
                float m = -3.4e38f;
                for (int j = go0; j < go1; ++j) m = fmaxf(m, alpha[j]);
                float den = 0.f;
                for (int j = go0; j < go1; ++j) {
                    float e = expf(alpha[j] - m);
                    alpha[j] = e;
                    den += e;
                }
                inv = 1.f / den;
            }
            invd[tid] = inv;
        }
        __syncthreads();

        // Phase C: warp-per-gene, within-gene ILP-2 accumulator chains
        for (int g = warp; g < N_GENES; g += 16) {
            int o0 = soff[g], o1 = soff[g + 1];
            float acc0 = 0.f, acc1 = 0.f;
            int j = o0;
            for (; j + 2 <= o1; j += 2) {
                int s0 = sedge[j] & 0xffff;
                int s1 = sedge[j + 1] & 0xffff;
                acc0 = fmaf(alpha[j], kvs[s0 * 33 + lane], acc0);
                acc1 = fmaf(alpha[j + 1], kvs[s1 * 33 + lane], acc1);
            }
            if (j < o1) {
                int s0 = sedge[j] & 0xffff;
                acc0 = fmaf(alpha[j], kvs[s0 * 33 + lane], acc0);
            }
            ob[g * D + hb + lane] = (acc0 + acc1) * invd[g];
        }
    }
}

// ---------------- K6: low_out = LN(attn+skip+bskip) + gene_agg fused -------
__global__ void __launch_bounds__(512) k_lowout(const float* __restrict__ lng,
        const float* __restrict__ lnb, const float* __restrict__ bsk,
        const float* __restrict__ aw, const float* __restrict__ ab_) {
    __shared__ float part[16 * D];
    __shared__ float mvec[D];
    int c = blockIdx.x, tid = threadIdx.x;
    int lane = tid & 31, warp = tid >> 5;
    float4 gg = *(const float4*)(lng + lane * 4);
    float4 bb = *(const float4*)(lnb + lane * 4);
    float4 bs = *(const float4*)(bsk + lane * 4);
    float4 ls = make_float4(0.f, 0.f, 0.f, 0.f);
    const float* ab = g_attn + (size_t)c * N_GENES * D;
    const float* sb = g_skip + (size_t)c * N_GENES * D;
    float* lo = g_low_out + (size_t)c * N_GENES * D;
    for (int g = warp; g < N_GENES; g += 16) {
        float4 a = *(const float4*)(ab + g * D + lane * 4);
        float4 sk = *(const float4*)(sb + g * D + lane * 4);
        float4 x = make_float4(a.x + sk.x + bs.x, a.y + sk.y + bs.y,
                               a.z + sk.z + bs.z, a.w + sk.w + bs.w);
        float sum = warpSum(x.x + x.y + x.z + x.w);
        float sq = warpSum(x.x * x.x + x.y * x.y + x.z * x.z + x.w * x.w);
        float mean = sum * (1.f / D);
        float var = sq * (1.f / D) - mean * mean;
        float inv = rsqrtf(var + 1e-5f);
        float4 y;
        y.x = (x.x - mean) * inv * gg.x + bb.x;
        y.y = (x.y - mean) * inv * gg.y + bb.y;
        y.z = (x.z - mean) * inv * gg.z + bb.z;
        y.w = (x.w - mean) * inv * gg.w + bb.w;
        *(float4*)(lo + g * D + lane * 4) = y;
        ls.x += y.x; ls.y += y.y; ls.z += y.z; ls.w += y.w;
    }
    part[warp * D + lane * 4 + 0] = ls.x;
    part[warp * D + lane * 4 + 1] = ls.y;
    part[warp * D + lane * 4 + 2] = ls.z;
    part[warp * D + lane * 4 + 3] = ls.w;
    __syncthreads();
    if (tid < D) {
        float s = 0.f;
#pragma unroll
        for (int w = 0; w < 16; w++) s += part[w * D + tid];
        mvec[tid] = s * (1.f / N_GENES);
    }
    __syncthreads();
    if (tid < D) {
        float t = ab_[tid];
#pragma unroll 4
        for (int k = 0; k < D; ++k) t = fmaf(mvec[k], aw[k * D + tid], t);
        g_gene_agg[c * D + tid] = geluf(t);
    }
}

// ---------------- K8: 6 cross projections as tf32 GEMMs ----------------
__global__ void __launch_bounds__(256) k_cross6(const float* __restrict__ cw) {
    extern __shared__ float sm[];
    float* As = sm;
    float* Bs = sm + 128 * PAD_A;
    int tid = threadIdx.x;
    int warp = tid >> 5;
    int wm = warp >> 1, wn = warp & 1;
    int row0 = blockIdx.x * 128;
    int mat = blockIdx.y;
    const float* A = (mat == 1 || mat == 2 || mat == 3) ? g_gene_agg : g_high_out;
    const float* B = cw + mat * 16384;

    for (int i = tid; i < 128 * 32; i += 256) {
        int r = i >> 5, ch = i & 31;
        cp16(As + r * PAD_A + ch * 4, A + (row0 + r) * 128 + ch * 4);
        cp16(Bs + r * PAD_B + ch * 4, B + r * 128 + ch * 4);
    }
    CP_COMMIT();
    CP_WAIT0();
    __syncthreads();

    FragC acc[2][4];
#pragma unroll
    for (int i = 0; i < 2; i++)
#pragma unroll
        for (int j = 0; j < 4; j++) wmma::fill_fragment(acc[i][j], 0.f);
#pragma unroll
    for (int k0 = 0; k0 < 128; k0 += 8) {
        FragA a[2];
#pragma unroll
        for (int i = 0; i < 2; i++)
            wmma::load_matrix_sync(a[i], As + (wm * 32 + i * 16) * PAD_A + k0, PAD_A);
        FragB b[4];
#pragma unroll
        for (int j = 0; j < 4; j++)
            wmma::load_matrix_sync(b[j], Bs + k0 * PAD_B + wn * 64 + j * 16, PAD_B);
#pragma unroll
        for (int i = 0; i < 2; i++)
#pragma unroll
            for (int j = 0; j < 4; j++)
                wmma::mma_sync(acc[i][j], a[i], b[j], acc[i][j]);
    }
    float* Out = g_cross6 + mat * N_CELLS * D;
#pragma unroll
    for (int i = 0; i < 2; i++)
#pragma unroll
        for (int j = 0; j < 4; j++)
            wmma::store_matrix_sync(Out + (row0 + wm * 32 + i * 16) * 128 + wn * 64 + j * 16,
                                    acc[i][j], 128, wmma::mem_row_major);
}

// ---------------- K9: gating + high_new LN + low_cross ----------------
__global__ void k_gate(const float* __restrict__ high_emb, const float* __restrict__ cb,
                       const float* __restrict__ nhg, const float* __restrict__ nhb,
                       float* __restrict__ out_high) {
    __shared__ float red[16];
    int c = blockIdx.x, tid = threadIdx.x;
    int lane = tid & 31, warp = tid >> 5;
    const float* base = g_cross6 + c * D + tid;
    float q1 = base[0] + cb[tid];
    float k1 = base[1 * N_CELLS * D] + cb[D + tid];
    float v1 = base[2 * N_CELLS * D] + cb[2 * D + tid];
    float q2 = base[3 * N_CELLS * D] + cb[3 * D + tid];
    float k2 = base[4 * N_CELLS * D] + cb[4 * D + tid];
    float v2 = base[5 * N_CELLS * D] + cb[5 * D + tid];
    float p1 = warpSum(q1 * k1);
    float p2 = warpSum(q2 * k2);
    if (lane == 0) { red[warp] = p1; red[8 + warp] = p2; }
    __syncthreads();
    float s1 = red[0] + red[1] + red[2] + red[3];
    float s2 = red[8] + red[9] + red[10] + red[11];
    const float sc = 0.08838834764831845f;
    float g1 = sigmoidf_(s1 * sc);
    float g2 = sigmoidf_(s2 * sc);
    g_low_cross[c * D + tid] = g2 * v2;
    float x = high_emb[c * D + tid] + g_high_out[c * D + tid] + g1 * v1;
    float bs_ = warpSum(x);
    float bq_ = warpSum(x * x);
    __syncthreads();
    if (lane == 0) { red[warp] = bs_; red[8 + warp] = bq_; }
    __syncthreads();
    float sum = red[0] + red[1] + red[2] + red[3];
    float sq = red[8] + red[9] + red[10] + red[11];
    float mean = sum * (1.f / D);
    float var = sq * (1.f / D) - mean * mean;
    out_high[c * D + tid] = (x - mean) * rsqrtf(var + 1e-5f) * nhg[tid] + nhb[tid];
}

// ---------------- K10: low_new = LN(low_emb + low_out + low_cross) ----------
__global__ void k_lownew(const float* __restrict__ low_emb,
                         const float* __restrict__ nlg, const float* __restrict__ nlb,
                         float* __restrict__ out_low) {
    int tid = threadIdx.x, lane = tid & 31, warp = tid >> 5;
    int row = blockIdx.x * 8 + warp;
    int c = row >> 8;
    float4 gg = *(const float4*)(nlg + lane * 4);
    float4 bb = *(const float4*)(nlb + lane * 4);
    float4 le = *(const float4*)(low_emb + (size_t)row * D + lane * 4);
    float4 lo = *(const float4*)(g_low_out + (size_t)row * D + lane * 4);
    float4 lc = *(const float4*)(g_low_cross + c * D + lane * 4);
    float4 x = make_float4(le.x + lo.x + lc.x, le.y + lo.y + lc.y,
                           le.z + lo.z + lc.z, le.w + lo.w + lc.w);
    float sum = warpSum(x.x + x.y + x.z + x.w);
    float sq = warpSum(x.x * x.x + x.y * x.y + x.z * x.z + x.w * x.w);
    float mean = sum * (1.f / D);
    float var = sq * (1.f / D) - mean * mean;
    float inv = rsqrtf(var + 1e-5f);
    float4 y;
    y.x = (x.x - mean) * inv * gg.x + bb.x;
    y.y = (x.y - mean) * inv * gg.y + bb.y;
    y.z = (x.z - mean) * inv * gg.z + bb.z;
    y.w = (x.w - mean) * inv * gg.w + bb.w;
    *(float4*)(out_low + (size_t)row * D + lane * 4) = y;
}

// ---------------- host ----------------
extern "C" void kernel_launch(void* const* d_in, const int* in_sizes, int n_in,
                              void* d_out, int out_size) {
    const float* high = (const float*)d_in[0];
    const float* low = (const float*)d_in[1];
    const int* sp = (const int*)d_in[2];
    const int* grn = (const int*)d_in[3];
    const float* gin_w1 = (const float*)d_in[4];
    const float* gin_b1 = (const float*)d_in[5];
    const float* gin_w2 = (const float*)d_in[6];
    const float* gin_b2 = (const float*)d_in[7];
    const float* gin_eps = (const float*)d_in[8];
    const float* gin_lng = (const float*)d_in[9];
    const float* gin_lnb = (const float*)d_in[10];
    const float* wq = (const float*)d_in[11];
    const float* bq = (const float*)d_in[12];
    const float* wk = (const float*)d_in[13];
    const float* bk = (const float*)d_in[14];
    const float* wv = (const float*)d_in[15];
    const float* bv = (const float*)d_in[16];
    const float* wsk = (const float*)d_in[17];
    const float* bsk = (const float*)d_in[18];
    const float* tclng = (const float*)d_in[19];
    const float* tclnb = (const float*)d_in[20];
    const float* cw = (const float*)d_in[21];
    const float* cb = (const float*)d_in[22];
    const float* aw = (const float*)d_in[23];
    const float* ab = (const float*)d_in[24];
    const float* nhg = (const float*)d_in[25];
    const float* nhb = (const float*)d_in[26];
    const float* nlg = (const float*)d_in[27];
    const float* nlb = (const float*)d_in[28];

    float* out_high = (float*)d_out;
    float* out_low = out_high + N_CELLS * D;

    int smem_gemm1 = (128 * PAD_A + 128 * PAD_B) * (int)sizeof(float);
    int smem_proj = (2 * 128 * PAD_H) * (int)sizeof(__half);
    cudaFuncSetAttribute(k_gin1, cudaFuncAttributeMaxDynamicSharedMemorySize, smem_gemm1);
    cudaFuncSetAttribute(k_gin2, cudaFuncAttributeMaxDynamicSharedMemorySize, smem_gemm1);
    cudaFuncSetAttribute(k_proj, cudaFuncAttributeMaxDynamicSharedMemorySize, smem_proj);
    cudaFuncSetAttribute(k_cross6, cudaFuncAttributeMaxDynamicSharedMemorySize, smem_gemm1);
    int smem_attn = (2 * N_GENES * 33 + E_GRN + N_GENES) * (int)sizeof(float)
                    + (E_GRN + N_GENES + 1) * (int)sizeof(int);
    cudaFuncSetAttribute(k_attn, cudaFuncAttributeMaxDynamicSharedMemorySize, smem_attn);

    cudaStream_t s1;
    cudaStreamCreateWithFlags(&s1, cudaStreamNonBlocking);
    cudaEvent_t evFork, evJoin;
    cudaEventCreateWithFlags(&evFork, cudaEventDisableTiming);
    cudaEventCreateWithFlags(&evJoin, cudaEventDisableTiming);

    cudaEventRecord(evFork, 0);
    cudaStreamWaitEvent(s1, evFork, 0);

    // side stream: high-level path
    k_zero<<<64, 1024, 0, s1>>>();
    k_scatter<<<(E_SP * D) / 256, 256, 0, s1>>>(high, sp);
    k_gin1<<<dim3(4, 2), 256, smem_gemm1, s1>>>(high, gin_w1, gin_b1, gin_eps);
    k_gin2<<<4, 256, smem_gemm1, s1>>>(gin_w2, gin_b2, gin_lng, gin_lnb);
    cudaEventRecord(evJoin, s1);

    // main stream: low-level path
    k_csr<<<1, 256>>>(grn);
    k_proj<<<dim3((N_CELLS * N_GENES) / 128, 4), 256, smem_proj>>>(low, wq, wk, wv, wsk);
    k_attn<<<dim3(N_CELLS, 2), 512, smem_attn>>>(bq, bk, bv);
    k_lowout<<<N_CELLS, 512>>>(tclng, tclnb, bsk, aw, ab);

    cudaStreamWaitEvent(0, evJoin, 0);
    k_cross6<<<dim3(4, 6), 256, smem_gemm1>>>(cw);
    k_gate<<<N_CELLS, 128>>>(high, cb, nhg, nhb, out_high);
    k_lownew<<<(N_CELLS * N_GENES) / 8, 256>>>(low, nlg, nlb, out_low);
}

// round 16
// speedup vs baseline: 1.2247x; 1.2247x over previous
#include <cuda_runtime.h>
#include <cuda_fp16.h>
#include <cstdint>
#include <mma.h>
#include <math.h>

using namespace nvcuda;

#define N_CELLS 512
#define N_GENES 256
#define D 128
#define HEADS 4
#define HD 32
#define E_SP 8192
#define E_GRN 2048

#define PAD_A 132
#define PAD_B 136
#define PAD_AH 136
#define PAD_BH 72

// ---------------- scratch ----------------
__device__ float g_agg[N_CELLS * D];
__device__ float g_hid[N_CELLS * 256];
__device__ float g_high_out[N_CELLS * D];
__device__ float g_q[N_CELLS * N_GENES * D];
__device__ float g_k[N_CELLS * N_GENES * D];
__device__ float g_v[N_CELLS * N_GENES * D];
__device__ float g_skip[N_CELLS * N_GENES * D];
__device__ float g_attn[N_CELLS * N_GENES * D];
__device__ float g_low_out[N_CELLS * N_GENES * D];
__device__ float g_gene_agg[N_CELLS * D];
__device__ float g_low_cross[N_CELLS * D];
__device__ float g_cross6[6 * N_CELLS * D];
__device__ int g_off[N_GENES + 1];
__device__ int g_edge[E_GRN];

// ---------------- helpers ----------------
__device__ __forceinline__ float geluf(float x) {
    return 0.5f * x * (1.f + erff(x * 0.7071067811865476f));
}
__device__ __forceinline__ float sigmoidf_(float x) {
    return 1.f / (1.f + expf(-x));
}
__device__ __forceinline__ float warpSum(float v) {
#pragma unroll
    for (int o = 16; o; o >>= 1) v += __shfl_xor_sync(0xffffffffu, v, o);
    return v;
}
__device__ __forceinline__ void cp16(void* smem, const void* g) {
    unsigned s = (unsigned)__cvta_generic_to_shared(smem);
    asm volatile("cp.async.cg.shared.global [%0], [%1], 16;\n" :: "r"(s), "l"(g));
}
#define CP_COMMIT() asm volatile("cp.async.commit_group;\n" ::: "memory")
#define CP_WAIT0()  asm volatile("cp.async.wait_group 0;\n" ::: "memory")

typedef wmma::fragment<wmma::matrix_a, 16, 16, 8, wmma::precision::tf32, wmma::row_major> FragA;
typedef wmma::fragment<wmma::matrix_b, 16, 16, 8, wmma::precision::tf32, wmma::row_major> FragB;
typedef wmma::fragment<wmma::accumulator, 16, 16, 8, float> FragC;
typedef wmma::fragment<wmma::matrix_a, 16, 16, 16, __half, wmma::row_major> FragAH;
typedef wmma::fragment<wmma::matrix_b, 16, 16, 16, __half, wmma::row_major> FragBH;
typedef wmma::fragment<wmma::accumulator, 16, 16, 16, float> FragCH;

// ---------------- K0: zero spatial agg ----------------
__global__ void k_zero() {
    int i = blockIdx.x * blockDim.x + threadIdx.x;
    if (i < N_CELLS * D) g_agg[i] = 0.f;
}

// ---------------- K1: spatial scatter-add ----------------
__global__ void k_scatter(const float* __restrict__ high, const int* __restrict__ sp) {
    int idx = blockIdx.x * blockDim.x + threadIdx.x;
    if (idx >= E_SP * D) return;
    int e = idx >> 7, d = idx & 127;
    int s = sp[e];
    int t = sp[E_SP + e];
    atomicAdd(&g_agg[t * D + d], high[s * D + d]);
}

// ---------------- K2: build CSR over grn edges (packed src|dst) -------
__global__ void k_csr(const int* __restrict__ grn) {
    __shared__ int cnt[N_GENES];
    __shared__ int cur[N_GENES];
    int tid = threadIdx.x;
    if (tid < N_GENES) cnt[tid] = 0;
    __syncthreads();
    for (int e = tid; e < E_GRN; e += blockDim.x) atomicAdd(&cnt[grn[E_GRN + e]], 1);
    __syncthreads();
    if (tid == 0) {
        int run = 0;
        for (int g = 0; g < N_GENES; ++g) {
            g_off[g] = run;
            cur[g] = run;
            run += cnt[g];
        }
        g_off[N_GENES] = run;
    }
    __syncthreads();
    for (int e = tid; e < E_GRN; e += blockDim.x) {
        int dg = grn[E_GRN + e];
        int p = atomicAdd(&cur[dg], 1);
        g_edge[p] = grn[e] | (dg << 16);
    }
}

// ---------------- K3a: GIN layer-1 GEMM + gelu ----------------
__global__ void __launch_bounds__(256) k_gin1(const float* __restrict__ high,
        const float* __restrict__ w1, const float* __restrict__ b1,
        const float* __restrict__ epsp) {
    extern __shared__ float sm[];
    float* As = sm;
    float* Bs = sm + 128 * PAD_A;
    int tid = threadIdx.x;
    int warp = tid >> 5;
    int wm = warp >> 1, wn = warp & 1;
    int row0 = blockIdx.x * 128;
    int n0 = blockIdx.y * 128;
    float ep = 1.f + epsp[0];

    for (int i = tid; i < 128 * 32; i += 256) {
        int k = i >> 5, ch = i & 31;
        cp16(Bs + k * PAD_B + ch * 4, w1 + k * 256 + n0 + ch * 4);
    }
    CP_COMMIT();
    for (int i = tid; i < 128 * 32; i += 256) {
        int r = i >> 5, ch = i & 31;
        float4 h4 = *(const float4*)(high + (row0 + r) * 128 + ch * 4);
        float4 a4 = *(const float4*)(g_agg + (row0 + r) * 128 + ch * 4);
        float* dst = As + r * PAD_A + ch * 4;
        dst[0] = fmaf(ep, h4.x, a4.x);
        dst[1] = fmaf(ep, h4.y, a4.y);
        dst[2] = fmaf(ep, h4.z, a4.z);
        dst[3] = fmaf(ep, h4.w, a4.w);
    }
    CP_WAIT0();
    __syncthreads();

    FragC acc[2][4];
#pragma unroll
    for (int i = 0; i < 2; i++)
#pragma unroll
        for (int j = 0; j < 4; j++) wmma::fill_fragment(acc[i][j], 0.f);
#pragma unroll
    for (int k0 = 0; k0 < 128; k0 += 8) {
        FragA a[2];
#pragma unroll
        for (int i = 0; i < 2; i++)
            wmma::load_matrix_sync(a[i], As + (wm * 32 + i * 16) * PAD_A + k0, PAD_A);
        FragB b[4];
#pragma unroll
        for (int j = 0; j < 4; j++)
            wmma::load_matrix_sync(b[j], Bs + k0 * PAD_B + wn * 64 + j * 16, PAD_B);
#pragma unroll
        for (int i = 0; i < 2; i++)
#pragma unroll
            for (int j = 0; j < 4; j++)
                wmma::mma_sync(acc[i][j], a[i], b[j], acc[i][j]);
    }
    __syncthreads();
#pragma unroll
    for (int i = 0; i < 2; i++)
#pragma unroll
        for (int j = 0; j < 4; j++)
            wmma::store_matrix_sync(As + (wm * 32 + i * 16) * PAD_A + wn * 64 + j * 16,
                                    acc[i][j], PAD_A, wmma::mem_row_major);
    __syncthreads();
    for (int i = tid; i < 128 * 128; i += 256) {
        int r = i >> 7, n = i & 127;
        g_hid[(row0 + r) * 256 + n0 + n] = geluf(As[r * PAD_A + n] + b1[n0 + n]);
    }
}

// ---------------- K3b: GIN layer-2 GEMM + LN ----------------
__global__ void __launch_bounds__(256) k_gin2(
        const float* __restrict__ w2, const float* __restrict__ b2,
        const float* __restrict__ lng, const float* __restrict__ lnb) {
    extern __shared__ float sm[];
    float* As = sm;
    float* Bs = sm + 128 * PAD_A;
    int tid = threadIdx.x;
    int warp = tid >> 5, lane = tid & 31;
    int wm = warp >> 1, wn = warp & 1;
    int row0 = blockIdx.x * 128;

    FragC acc[2][4];
#pragma unroll
    for (int i = 0; i < 2; i++)
#pragma unroll
        for (int j = 0; j < 4; j++) wmma::fill_fragment(acc[i][j], 0.f);

    for (int kc = 0; kc < 256; kc += 128) {
        for (int i = tid; i < 128 * 32; i += 256) {
            int r = i >> 5, ch = i & 31;
            cp16(As + r * PAD_A + ch * 4, g_hid + (row0 + r) * 256 + kc + ch * 4);
            cp16(Bs + r * PAD_B + ch * 4, w2 + (kc + r) * 128 + ch * 4);
        }
        CP_COMMIT();
        CP_WAIT0();
        __syncthreads();
#pragma unroll
        for (int k0 = 0; k0 < 128; k0 += 8) {
            FragA a[2];
#pragma unroll
            for (int i = 0; i < 2; i++)
                wmma::load_matrix_sync(a[i], As + (wm * 32 + i * 16) * PAD_A + k0, PAD_A);
            FragB b[4];
#pragma unroll
            for (int j = 0; j < 4; j++)
                wmma::load_matrix_sync(b[j], Bs + k0 * PAD_B + wn * 64 + j * 16, PAD_B);
#pragma unroll
            for (int i = 0; i < 2; i++)
#pragma unroll
                for (int j = 0; j < 4; j++)
                    wmma::mma_sync(acc[i][j], a[i], b[j], acc[i][j]);
        }
        __syncthreads();
    }
#pragma unroll
    for (int i = 0; i < 2; i++)
#pragma unroll
        for (int j = 0; j < 4; j++)
            wmma::store_matrix_sync(As + (wm * 32 + i * 16) * PAD_A + wn * 64 + j * 16,
                                    acc[i][j], PAD_A, wmma::mem_row_major);
    __syncthreads();
    float4 bb2 = *(const float4*)(b2 + lane * 4);
    float4 gg = *(const float4*)(lng + lane * 4);
    float4 bb = *(const float4*)(lnb + lane * 4);
    for (int r = warp; r < 128; r += 8) {
        float4 x = *(float4*)(As + r * PAD_A + lane * 4);
        x.x += bb2.x; x.y += bb2.y; x.z += bb2.z; x.w += bb2.w;
        float sum = warpSum(x.x + x.y + x.z + x.w);
        float sq = warpSum(x.x * x.x + x.y * x.y + x.z * x.z + x.w * x.w);
        float mean = sum * (1.f / D);
        float var = sq * (1.f / D) - mean * mean;
        float inv = rsqrtf(var + 1e-5f);
        float4 y;
        y.x = (x.x - mean) * inv * gg.x + bb.x;
        y.y = (x.y - mean) * inv * gg.y + bb.y;
        y.z = (x.z - mean) * inv * gg.z + bb.z;
        y.w = (x.w - mean) * inv * gg.w + bb.w;
        *(float4*)(g_high_out + (size_t)(row0 + r) * 128 + lane * 4) = y;
    }
}

// ---------------- K4: projection GEMM — fp16, 512 threads (16 warps) -------
// grid (1024 row-tiles, 2 col-halves, 4 weights). Warp tile 16x32 (acc 1x2).
__global__ void __launch_bounds__(512) k_proj(const float* __restrict__ A,
        const float* __restrict__ wq, const float* __restrict__ wk,
        const float* __restrict__ wv, const float* __restrict__ ws) {
    extern __shared__ __half smh[];
    __half* As = smh;                     // [128][PAD_AH]
    __half* Bs = smh + 128 * PAD_AH;      // [128][PAD_BH]
    int tid = threadIdx.x;
    int warp = tid >> 5;
    int wm = warp >> 1, wn = warp & 1;    // 8x2 warps; warp tile 16x32
    size_t row0 = (size_t)blockIdx.x * 128;
    int n0 = blockIdx.y * 64;
    int w = blockIdx.z;

    const float* Ws[4] = {wq, wk, wv, ws};
    float* Outs[4] = {g_q, g_k, g_v, g_skip};
    const float* B = Ws[w];

    for (int i = tid; i < 128 * 32; i += 512) {
        int r = i >> 5, ch = i & 31;
        float4 v = *(const float4*)(A + (row0 + r) * 128 + ch * 4);
        __half2* dst = (__half2*)(As + r * PAD_AH + ch * 4);
        dst[0] = __floats2half2_rn(v.x, v.y);
        dst[1] = __floats2half2_rn(v.z, v.w);
    }
    for (int i = tid; i < 128 * 16; i += 512) {
        int k = i >> 4, ch = i & 15;
        float4 v = *(const float4*)(B + k * 128 + n0 + ch * 4);
        __half2* dst = (__half2*)(Bs + k * PAD_BH + ch * 4);
        dst[0] = __floats2half2_rn(v.x, v.y);
        dst[1] = __floats2half2_rn(v.z, v.w);
    }
    __syncthreads();

    FragCH acc[2];
#pragma unroll
    for (int j = 0; j < 2; j++) wmma::fill_fragment(acc[j], 0.f);
#pragma unroll
    for (int k0 = 0; k0 < 128; k0 += 16) {
        FragAH a;
        wmma::load_matrix_sync(a, As + (wm * 16) * PAD_AH + k0, PAD_AH);
        FragBH b[2];
#pragma unroll
        for (int j = 0; j < 2; j++)
            wmma::load_matrix_sync(b[j], Bs + k0 * PAD_BH + wn * 32 + j * 16, PAD_BH);
#pragma unroll
        for (int j = 0; j < 2; j++)
            wmma::mma_sync(acc[j], a, b[j], acc[j]);
    }
    float* Out = Outs[w];
#pragma unroll
    for (int j = 0; j < 2; j++)
        wmma::store_matrix_sync(Out + (row0 + wm * 16) * 128 + n0 + wn * 32 + j * 16,
                                acc[j], 128, wmma::mem_row_major);
}

// ---------------- K5: attention — head-split (512 cells, 2) ----------------
__global__ void __launch_bounds__(512) k_attn(const float* __restrict__ bq,
                                              const float* __restrict__ bk,
                                              const float* __restrict__ bv) {
    extern __shared__ float sm[];
    float* qs = sm;
    float* kvs = qs + N_GENES * 33;
    float* alpha = kvs + N_GENES * 33;
    float* invd = alpha + E_GRN;
    int* sedge = (int*)(invd + N_GENES);
    int* soff = sedge + E_GRN;
    int c = blockIdx.x, tid = threadIdx.x;
    int lane = tid & 31, warp = tid >> 5;
    int h0 = blockIdx.y * 2;
    for (int i = tid; i < E_GRN; i += 512) sedge[i] = g_edge[i];
    for (int i = tid; i <= N_GENES; i += 512) soff[i] = g_off[i];
    const float* qb = g_q + (size_t)c * N_GENES * D;
    const float* kb = g_k + (size_t)c * N_GENES * D;
    const float* vb = g_v + (size_t)c * N_GENES * D;
    float* ob = g_attn + (size_t)c * N_GENES * D;
    int go0 = 0, go1 = 0;
    if (tid < N_GENES) { go0 = g_off[tid]; go1 = g_off[tid + 1]; }

    for (int h = h0; h < h0 + 2; ++h) {
        __syncthreads();
        int hb = h * HD;
        for (int i = tid; i < N_GENES * 8; i += 512) {
            int g = i >> 3, dq = (i & 7) * 4;
            float4 qv = *(const float4*)(qb + g * D + hb + dq);
            float4 kv = *(const float4*)(kb + g * D + hb + dq);
            float4 b1 = *(const float4*)(bq + hb + dq);
            float4 b2 = *(const float4*)(bk + hb + dq);
            float* qd = qs + g * 33 + dq;
            float* kd = kvs + g * 33 + dq;
            qd[0] = qv.x + b1.x; qd[1] = qv.y + b1.y; qd[2] = qv.z + b1.z; qd[3] = qv.w + b1.w;
            kd[0] = kv.x + b2.x; kd[1] = kv.y + b2.y; kd[2] = kv.z + b2.z; kd[3] = kv.w + b2.w;
        }
        __syncthreads();

        for (int e = tid; e < E_GRN; e += 512) {
            int pk = sedge[e];
            int s = pk & 0xffff, dg = pk >> 16;
            const float* qr = qs + dg * 33;
            const float* kr = kvs + s * 33;
            float t0 = 0.f, t1 = 0.f;
#pragma unroll
            for (int d = 0; d < HD; d += 2) {
                t0 = fmaf(qr[d], kr[d], t0);
                t1 = fmaf(qr[d + 1], kr[d + 1], t1);
            }
            alpha[e] = (t0 + t1) * 0.17677669529663689f;
        }
        __syncthreads();

        for (int i = tid; i < N_GENES * 8; i += 512) {
            int g = i >> 3, dq = (i & 7) * 4;
            float4 vv = *(const float4*)(vb + g * D + hb + dq);
            float4 b3 = *(const float4*)(bv + hb + dq);
            float* vd = kvs + g * 33 + dq;
            vd[0] = vv.x + b3.x; vd[1] = vv.y + b3.y; vd[2] = vv.z + b3.z; vd[3] = vv.w + b3.w;
        }
        if (tid < N_GENES) {
            float inv = 0.f;
            if (go1 > go0) {
                float m = -3.4e38f;
                for (int j = go0; j < go1; ++j) m = fmaxf(m, alpha[j]);
                float den = 0.f;
                for (int j = go0; j < go1; ++j) {
                    float e = expf(alpha[j] - m);
                    alpha[j] = e;
                    den += e;
                }
                inv = 1.f / den;
            }
            invd[tid] = inv;
        }
        __syncthreads();

        for (int g = warp; g < N_GENES; g += 16) {
            int o0 = soff[g], o1 = soff[g + 1];
            float acc = 0.f;
            for (int j = o0; j < o1; ++j) {
                int s = sedge[j] & 0xffff;
                acc = fmaf(alpha[j], kvs[s * 33 + lane], acc);
            }
            ob[g * D + hb + lane] = acc * invd[g];
        }
    }
}

// ---------------- K6: low_out = LN(attn+skip+bskip) + gene_agg fused -------
__global__ void __launch_bounds__(512) k_lowout(const float* __restrict__ lng,
        const float* __restrict__ lnb, const float* __restrict__ bsk,
        const float* __restrict__ aw, const float* __restrict__ ab_) {
    __shared__ float part[16 * D];
    __shared__ float mvec[D];
    int c = blockIdx.x, tid = threadIdx.x;
    int lane = tid & 31, warp = tid >> 5;
    float4 gg = *(const float4*)(lng + lane * 4);
    float4 bb = *(const float4*)(lnb + lane * 4);
    float4 bs = *(const float4*)(bsk + lane * 4);
    float4 ls = make_float4(0.f, 0.f, 0.f, 0.f);
    const float* ab = g_attn + (size_t)c * N_GENES * D;
    const float* sb = g_skip + (size_t)c * N_GENES * D;
    float* lo = g_low_out + (size_t)c * N_GENES * D;
    for (int g = warp; g < N_GENES; g += 16) {
        float4 a = *(const float4*)(ab + g * D + lane * 4);
        float4 sk = *(const float4*)(sb + g * D + lane * 4);
        float4 x = make_float4(a.x + sk.x + bs.x, a.y + sk.y + bs.y,
                               a.z + sk.z + bs.z, a.w + sk.w + bs.w);
        float sum = warpSum(x.x + x.y + x.z + x.w);
        float sq = warpSum(x.x * x.x + x.y * x.y + x.z * x.z + x.w * x.w);
        float mean = sum * (1.f / D);
        float var = sq * (1.f / D) - mean * mean;
        float inv = rsqrtf(var + 1e-5f);
        float4 y;
        y.x = (x.x - mean) * inv * gg.x + bb.x;
        y.y = (x.y - mean) * inv * gg.y + bb.y;
        y.z = (x.z - mean) * inv * gg.z + bb.z;
        y.w = (x.w - mean) * inv * gg.w + bb.w;
        *(float4*)(lo + g * D + lane * 4) = y;
        ls.x += y.x; ls.y += y.y; ls.z += y.z; ls.w += y.w;
    }
    part[warp * D + lane * 4 + 0] = ls.x;
    part[warp * D + lane * 4 + 1] = ls.y;
    part[warp * D + lane * 4 + 2] = ls.z;
    part[warp * D + lane * 4 + 3] = ls.w;
    __syncthreads();
    if (tid < D) {
        float s = 0.f;
#pragma unroll
        for (int w = 0; w < 16; w++) s += part[w * D + tid];
        mvec[tid] = s * (1.f / N_GENES);
    }
    __syncthreads();
    if (tid < D) {
        float t = ab_[tid];
#pragma unroll 4
        for (int k = 0; k < D; ++k) t = fmaf(mvec[k], aw[k * D + tid], t);
        g_gene_agg[c * D + tid] = geluf(t);
    }
}

// ---------------- K8: 6 cross projections as tf32 GEMMs ----------------
__global__ void __launch_bounds__(256) k_cross6(const float* __restrict__ cw) {
    extern __shared__ float sm[];
    float* As = sm;
    float* Bs = sm + 128 * PAD_A;
    int tid = threadIdx.x;
    int warp = tid >> 5;
    int wm = warp >> 1, wn = warp & 1;
    int row0 = blockIdx.x * 128;
    int mat = blockIdx.y;
    const float* A = (mat == 1 || mat == 2 || mat == 3) ? g_gene_agg : g_high_out;
    const float* B = cw + mat * 16384;

    for (int i = tid; i < 128 * 32; i += 256) {
        int r = i >> 5, ch = i & 31;
        cp16(As + r * PAD_A + ch * 4, A + (row0 + r) * 128 + ch * 4);
        cp16(Bs + r * PAD_B + ch * 4, B + r * 128 + ch * 4);
    }
    CP_COMMIT();
    CP_WAIT0();
    __syncthreads();

    FragC acc[2][4];
#pragma unroll
    for (int i = 0; i < 2; i++)
#pragma unroll
        for (int j = 0; j < 4; j++) wmma::fill_fragment(acc[i][j], 0.f);
#pragma unroll
    for (int k0 = 0; k0 < 128; k0 += 8) {
        FragA a[2];
#pragma unroll
        for (int i = 0; i < 2; i++)
            wmma::load_matrix_sync(a[i], As + (wm * 32 + i * 16) * PAD_A + k0, PAD_A);
        FragB b[4];
#pragma unroll
        for (int j = 0; j < 4; j++)
            wmma::load_matrix_sync(b[j], Bs + k0 * PAD_B + wn * 64 + j * 16, PAD_B);
#pragma unroll
        for (int i = 0; i < 2; i++)
#pragma unroll
            for (int j = 0; j < 4; j++)
                wmma::mma_sync(acc[i][j], a[i], b[j], acc[i][j]);
    }
    float* Out = g_cross6 + mat * N_CELLS * D;
#pragma unroll
    for (int i = 0; i < 2; i++)
#pragma unroll
        for (int j = 0; j < 4; j++)
            wmma::store_matrix_sync(Out + (row0 + wm * 32 + i * 16) * 128 + wn * 64 + j * 16,
                                    acc[i][j], 128, wmma::mem_row_major);
}

// ---------------- K9: gating + high_new LN + low_cross ----------------
__global__ void k_gate(const float* __restrict__ high_emb, const float* __restrict__ cb,
                       const float* __restrict__ nhg, const float* __restrict__ nhb,
                       float* __restrict__ out_high) {
    __shared__ float red[16];
    int c = blockIdx.x, tid = threadIdx.x;
    int lane = tid & 31, warp = tid >> 5;
    const float* base = g_cross6 + c * D + tid;
    float q1 = base[0] + cb[tid];
    float k1 = base[1 * N_CELLS * D] + cb[D + tid];
    float v1 = base[2 * N_CELLS * D] + cb[2 * D + tid];
    float q2 = base[3 * N_CELLS * D] + cb[3 * D + tid];
    float k2 = base[4 * N_CELLS * D] + cb[4 * D + tid];
    float v2 = base[5 * N_CELLS * D] + cb[5 * D + tid];
    float p1 = warpSum(q1 * k1);
    float p2 = warpSum(q2 * k2);
    if (lane == 0) { red[warp] = p1; red[8 + warp] = p2; }
    __syncthreads();
    float s1 = red[0] + red[1] + red[2] + red[3];
    float s2 = red[8] + red[9] + red[10] + red[11];
    const float sc = 0.08838834764831845f;
    float g1 = sigmoidf_(s1 * sc);
    float g2 = sigmoidf_(s2 * sc);
    g_low_cross[c * D + tid] = g2 * v2;
    float x = high_emb[c * D + tid] + g_high_out[c * D + tid] + g1 * v1;
    float bs_ = warpSum(x);
    float bq_ = warpSum(x * x);
    __syncthreads();
    if (lane == 0) { red[warp] = bs_; red[8 + warp] = bq_; }
    __syncthreads();
    float sum = red[0] + red[1] + red[2] + red[3];
    float sq = red[8] + red[9] + red[10] + red[11];
    float mean = sum * (1.f / D);
    float var = sq * (1.f / D) - mean * mean;
    out_high[c * D + tid] = (x - mean) * rsqrtf(var + 1e-5f) * nhg[tid] + nhb[tid];
}

// ---------------- K10: low_new = LN(low_emb + low_out + low_cross) ----------
__global__ void k_lownew(const float* __restrict__ low_emb,
                         const float* __restrict__ nlg, const float* __restrict__ nlb,
                         float* __restrict__ out_low) {
    int tid = threadIdx.x, lane = tid & 31, warp = tid >> 5;
    int row = blockIdx.x * 8 + warp;
    int c = row >> 8;
    float4 gg = *(const float4*)(nlg + lane * 4);
    float4 bb = *(const float4*)(nlb + lane * 4);
    float4 le = *(const float4*)(low_emb + (size_t)row * D + lane * 4);
    float4 lo = *(const float4*)(g_low_out + (size_t)row * D + lane * 4);
    float4 lc = *(const float4*)(g_low_cross + c * D + lane * 4);
    float4 x = make_float4(le.x + lo.x + lc.x, le.y + lo.y + lc.y,
                           le.z + lo.z + lc.z, le.w + lo.w + lc.w);
    float sum = warpSum(x.x + x.y + x.z + x.w);
    float sq = warpSum(x.x * x.x + x.y * x.y + x.z * x.z + x.w * x.w);
    float mean = sum * (1.f / D);
    float var = sq * (1.f / D) - mean * mean;
    float inv = rsqrtf(var + 1e-5f);
    float4 y;
    y.x = (x.x - mean) * inv * gg.x + bb.x;
    y.y = (x.y - mean) * inv * gg.y + bb.y;
    y.z = (x.z - mean) * inv * gg.z + bb.z;
    y.w = (x.w - mean) * inv * gg.w + bb.w;
    *(float4*)(out_low + (size_t)row * D + lane * 4) = y;
}

// ---------------- host ----------------
extern "C" void kernel_launch(void* const* d_in, const int* in_sizes, int n_in,
                              void* d_out, int out_size) {
    const float* high = (const float*)d_in[0];
    const float* low = (const float*)d_in[1];
    const int* sp = (const int*)d_in[2];
    const int* grn = (const int*)d_in[3];
    const float* gin_w1 = (const float*)d_in[4];
    const float* gin_b1 = (const float*)d_in[5];
    const float* gin_w2 = (const float*)d_in[6];
    const float* gin_b2 = (const float*)d_in[7];
    const float* gin_eps = (const float*)d_in[8];
    const float* gin_lng = (const float*)d_in[9];
    const float* gin_lnb = (const float*)d_in[10];
    const float* wq = (const float*)d_in[11];
    const float* bq = (const float*)d_in[12];
    const float* wk = (const float*)d_in[13];
    const float* bk = (const float*)d_in[14];
    const float* wv = (const float*)d_in[15];
    const float* bv = (const float*)d_in[16];
    const float* wsk = (const float*)d_in[17];
    const float* bsk = (const float*)d_in[18];
    const float* tclng = (const float*)d_in[19];
    const float* tclnb = (const float*)d_in[20];
    const float* cw = (const float*)d_in[21];
    const float* cb = (const float*)d_in[22];
    const float* aw = (const float*)d_in[23];
    const float* ab = (const float*)d_in[24];
    const float* nhg = (const float*)d_in[25];
    const float* nhb = (const float*)d_in[26];
    const float* nlg = (const float*)d_in[27];
    const float* nlb = (const float*)d_in[28];

    float* out_high = (float*)d_out;
    float* out_low = out_high + N_CELLS * D;

    int smem_gemm1 = (128 * PAD_A + 128 * PAD_B) * (int)sizeof(float);
    int smem_proj = (128 * PAD_AH + 128 * PAD_BH) * (int)sizeof(__half);
    cudaFuncSetAttribute(k_gin1, cudaFuncAttributeMaxDynamicSharedMemorySize, smem_gemm1);
    cudaFuncSetAttribute(k_gin2, cudaFuncAttributeMaxDynamicSharedMemorySize, smem_gemm1);
    cudaFuncSetAttribute(k_proj, cudaFuncAttributeMaxDynamicSharedMemorySize, smem_proj);
    cudaFuncSetAttribute(k_cross6, cudaFuncAttributeMaxDynamicSharedMemorySize, smem_gemm1);
    int smem_attn = (2 * N_GENES * 33 + E_GRN + N_GENES) * (int)sizeof(float)
                    + (E_GRN + N_GENES + 1) * (int)sizeof(int);
    cudaFuncSetAttribute(k_attn, cudaFuncAttributeMaxDynamicSharedMemorySize, smem_attn);

    cudaStream_t s1;
    cudaStreamCreateWithFlags(&s1, cudaStreamNonBlocking);
    cudaEvent_t evFork, evJoin;
    cudaEventCreateWithFlags(&evFork, cudaEventDisableTiming);
    cudaEventCreateWithFlags(&evJoin, cudaEventDisableTiming);

    cudaEventRecord(evFork, 0);
    cudaStreamWaitEvent(s1, evFork, 0);

    // side stream: high-level path
    k_zero<<<64, 1024, 0, s1>>>();
    k_scatter<<<(E_SP * D) / 256, 256, 0, s1>>>(high, sp);
    k_gin1<<<dim3(4, 2), 256, smem_gemm1, s1>>>(high, gin_w1, gin_b1, gin_eps);
    k_gin2<<<4, 256, smem_gemm1, s1>>>(gin_w2, gin_b2, gin_lng, gin_lnb);
    cudaEventRecord(evJoin, s1);

    // main stream: low-level path
    k_csr<<<1, 256>>>(grn);
    k_proj<<<dim3((N_CELLS * N_GENES) / 128, 2, 4), 512, smem_proj>>>(low, wq, wk, wv, wsk);
    k_attn<<<dim3(N_CELLS, 2), 512, smem_attn>>>(bq, bk, bv);
    k_lowout<<<N_CELLS, 512>>>(tclng, tclnb, bsk, aw, ab);

    cudaStreamWaitEvent(0, evJoin, 0);
    k_cross6<<<dim3(4, 6), 256, smem_gemm1>>>(cw);
    k_gate<<<N_CELLS, 128>>>(high, cb, nhg, nhb, out_high);
    k_lownew<<<(N_CELLS * N_GENES) / 8, 256>>>(low, nlg, nlb, out_low);
}

// round 17
// speedup vs baseline: 1.2408x; 1.0132x over previous
#include <cuda_runtime.h>
#include <cuda_fp16.h>
#include <cstdint>
#include <mma.h>
#include <math.h>

using namespace nvcuda;

#define N_CELLS 512
#define N_GENES 256
#define D 128
#define HEADS 4
#define HD 32
#define E_SP 8192
#define E_GRN 2048

#define PAD_A 132
#define PAD_B 136
#define PAD_AH 136
#define PAD_BH 72

// ---------------- scratch ----------------
__device__ float g_agg[N_CELLS * D];
__device__ float g_hid[N_CELLS * 256];
__device__ float g_high_out[N_CELLS * D];
__device__ float g_q[N_CELLS * N_GENES * D];
__device__ float g_k[N_CELLS * N_GENES * D];
__device__ float g_v[N_CELLS * N_GENES * D];
__device__ float g_skip[N_CELLS * N_GENES * D];
__device__ float g_attn[N_CELLS * N_GENES * D];
__device__ float g_low_out[N_CELLS * N_GENES * D];
__device__ float g_gene_agg[N_CELLS * D];
__device__ float g_low_cross[N_CELLS * D];
__device__ float g_cross6[6 * N_CELLS * D];
__device__ int g_off[N_GENES + 1];
__device__ int g_edge[E_GRN];

// ---------------- helpers ----------------
__device__ __forceinline__ float geluf(float x) {
    return 0.5f * x * (1.f + erff(x * 0.7071067811865476f));
}
__device__ __forceinline__ float sigmoidf_(float x) {
    return 1.f / (1.f + expf(-x));
}
__device__ __forceinline__ float warpSum(float v) {
#pragma unroll
    for (int o = 16; o; o >>= 1) v += __shfl_xor_sync(0xffffffffu, v, o);
    return v;
}
__device__ __forceinline__ void cp16(void* smem, const void* g) {
    unsigned s = (unsigned)__cvta_generic_to_shared(smem);
    asm volatile("cp.async.cg.shared.global [%0], [%1], 16;\n" :: "r"(s), "l"(g));
}
#define CP_COMMIT() asm volatile("cp.async.commit_group;\n" ::: "memory")
#define CP_WAIT0()  asm volatile("cp.async.wait_group 0;\n" ::: "memory")

typedef wmma::fragment<wmma::matrix_a, 16, 16, 8, wmma::precision::tf32, wmma::row_major> FragA;
typedef wmma::fragment<wmma::matrix_b, 16, 16, 8, wmma::precision::tf32, wmma::row_major> FragB;
typedef wmma::fragment<wmma::accumulator, 16, 16, 8, float> FragC;
typedef wmma::fragment<wmma::matrix_a, 16, 16, 16, __half, wmma::row_major> FragAH;
typedef wmma::fragment<wmma::matrix_b, 16, 16, 16, __half, wmma::row_major> FragBH;
typedef wmma::fragment<wmma::accumulator, 16, 16, 16, float> FragCH;

// ---------------- K0: zero spatial agg ----------------
__global__ void k_zero() {
    int i = blockIdx.x * blockDim.x + threadIdx.x;
    if (i < N_CELLS * D) g_agg[i] = 0.f;
}

// ---------------- K1: spatial scatter-add ----------------
__global__ void k_scatter(const float* __restrict__ high, const int* __restrict__ sp) {
    int idx = blockIdx.x * blockDim.x + threadIdx.x;
    if (idx >= E_SP * D) return;
    int e = idx >> 7, d = idx & 127;
    int s = sp[e];
    int t = sp[E_SP + e];
    atomicAdd(&g_agg[t * D + d], high[s * D + d]);
}

// ---------------- K2: build CSR over grn edges (packed src|dst) -------
__global__ void k_csr(const int* __restrict__ grn) {
    __shared__ int cnt[N_GENES];
    __shared__ int cur[N_GENES];
    int tid = threadIdx.x;
    if (tid < N_GENES) cnt[tid] = 0;
    __syncthreads();
    for (int e = tid; e < E_GRN; e += blockDim.x) atomicAdd(&cnt[grn[E_GRN + e]], 1);
    __syncthreads();
    if (tid == 0) {
        int run = 0;
        for (int g = 0; g < N_GENES; ++g) {
            g_off[g] = run;
            cur[g] = run;
            run += cnt[g];
        }
        g_off[N_GENES] = run;
    }
    __syncthreads();
    for (int e = tid; e < E_GRN; e += blockDim.x) {
        int dg = grn[E_GRN + e];
        int p = atomicAdd(&cur[dg], 1);
        g_edge[p] = grn[e] | (dg << 16);
    }
}

// ---------------- K3a: GIN layer-1 GEMM + gelu ----------------
__global__ void __launch_bounds__(256) k_gin1(const float* __restrict__ high,
        const float* __restrict__ w1, const float* __restrict__ b1,
        const float* __restrict__ epsp) {
    extern __shared__ float sm[];
    float* As = sm;
    float* Bs = sm + 128 * PAD_A;
    int tid = threadIdx.x;
    int warp = tid >> 5;
    int wm = warp >> 1, wn = warp & 1;
    int row0 = blockIdx.x * 128;
    int n0 = blockIdx.y * 128;
    float ep = 1.f + epsp[0];

    for (int i = tid; i < 128 * 32; i += 256) {
        int k = i >> 5, ch = i & 31;
        cp16(Bs + k * PAD_B + ch * 4, w1 + k * 256 + n0 + ch * 4);
    }
    CP_COMMIT();
    for (int i = tid; i < 128 * 32; i += 256) {
        int r = i >> 5, ch = i & 31;
        float4 h4 = *(const float4*)(high + (row0 + r) * 128 + ch * 4);
        float4 a4 = *(const float4*)(g_agg + (row0 + r) * 128 + ch * 4);
        float* dst = As + r * PAD_A + ch * 4;
        dst[0] = fmaf(ep, h4.x, a4.x);
        dst[1] = fmaf(ep, h4.y, a4.y);
        dst[2] = fmaf(ep, h4.z, a4.z);
        dst[3] = fmaf(ep, h4.w, a4.w);
    }
    CP_WAIT0();
    __syncthreads();

    FragC acc[2][4];
#pragma unroll
    for (int i = 0; i < 2; i++)
#pragma unroll
        for (int j = 0; j < 4; j++) wmma::fill_fragment(acc[i][j], 0.f);
#pragma unroll
    for (int k0 = 0; k0 < 128; k0 += 8) {
        FragA a[2];
#pragma unroll
        for (int i = 0; i < 2; i++)
            wmma::load_matrix_sync(a[i], As + (wm * 32 + i * 16) * PAD_A + k0, PAD_A);
        FragB b[4];
#pragma unroll
        for (int j = 0; j < 4; j++)
            wmma::load_matrix_sync(b[j], Bs + k0 * PAD_B + wn * 64 + j * 16, PAD_B);
#pragma unroll
        for (int i = 0; i < 2; i++)
#pragma unroll
            for (int j = 0; j < 4; j++)
                wmma::mma_sync(acc[i][j], a[i], b[j], acc[i][j]);
    }
    __syncthreads();
#pragma unroll
    for (int i = 0; i < 2; i++)
#pragma unroll
        for (int j = 0; j < 4; j++)
            wmma::store_matrix_sync(As + (wm * 32 + i * 16) * PAD_A + wn * 64 + j * 16,
                                    acc[i][j], PAD_A, wmma::mem_row_major);
    __syncthreads();
    for (int i = tid; i < 128 * 128; i += 256) {
        int r = i >> 7, n = i & 127;
        g_hid[(row0 + r) * 256 + n0 + n] = geluf(As[r * PAD_A + n] + b1[n0 + n]);
    }
}

// ---------------- K3b: GIN layer-2 GEMM + LN ----------------
__global__ void __launch_bounds__(256) k_gin2(
        const float* __restrict__ w2, const float* __restrict__ b2,
        const float* __restrict__ lng, const float* __restrict__ lnb) {
    extern __shared__ float sm[];
    float* As = sm;
    float* Bs = sm + 128 * PAD_A;
    int tid = threadIdx.x;
    int warp = tid >> 5, lane = tid & 31;
    int wm = warp >> 1, wn = warp & 1;
    int row0 = blockIdx.x * 128;

    FragC acc[2][4];
#pragma unroll
    for (int i = 0; i < 2; i++)
#pragma unroll
        for (int j = 0; j < 4; j++) wmma::fill_fragment(acc[i][j], 0.f);

    for (int kc = 0; kc < 256; kc += 128) {
        for (int i = tid; i < 128 * 32; i += 256) {
            int r = i >> 5, ch = i & 31;
            cp16(As + r * PAD_A + ch * 4, g_hid + (row0 + r) * 256 + kc + ch * 4);
            cp16(Bs + r * PAD_B + ch * 4, w2 + (kc + r) * 128 + ch * 4);
        }
        CP_COMMIT();
        CP_WAIT0();
        __syncthreads();
#pragma unroll
        for (int k0 = 0; k0 < 128; k0 += 8) {
            FragA a[2];
#pragma unroll
            for (int i = 0; i < 2; i++)
                wmma::load_matrix_sync(a[i], As + (wm * 32 + i * 16) * PAD_A + k0, PAD_A);
            FragB b[4];
#pragma unroll
            for (int j = 0; j < 4; j++)
                wmma::load_matrix_sync(b[j], Bs + k0 * PAD_B + wn * 64 + j * 16, PAD_B);
#pragma unroll
            for (int i = 0; i < 2; i++)
#pragma unroll
                for (int j = 0; j < 4; j++)
                    wmma::mma_sync(acc[i][j], a[i], b[j], acc[i][j]);
        }
        __syncthreads();
    }
#pragma unroll
    for (int i = 0; i < 2; i++)
#pragma unroll
        for (int j = 0; j < 4; j++)
            wmma::store_matrix_sync(As + (wm * 32 + i * 16) * PAD_A + wn * 64 + j * 16,
                                    acc[i][j], PAD_A, wmma::mem_row_major);
    __syncthreads();
    float4 bb2 = *(const float4*)(b2 + lane * 4);
    float4 gg = *(const float4*)(lng + lane * 4);
    float4 bb = *(const float4*)(lnb + lane * 4);
    for (int r = warp; r < 128; r += 8) {
        float4 x = *(float4*)(As + r * PAD_A + lane * 4);
        x.x += bb2.x; x.y += bb2.y; x.z += bb2.z; x.w += bb2.w;
        float sum = warpSum(x.x + x.y + x.z + x.w);
        float sq = warpSum(x.x * x.x + x.y * x.y + x.z * x.z + x.w * x.w);
        float mean = sum * (1.f / D);
        float var = sq * (1.f / D) - mean * mean;
        float inv = rsqrtf(var + 1e-5f);
        float4 y;
        y.x = (x.x - mean) * inv * gg.x + bb.x;
        y.y = (x.y - mean) * inv * gg.y + bb.y;
        y.z = (x.z - mean) * inv * gg.z + bb.z;
        y.w = (x.w - mean) * inv * gg.w + bb.w;
        *(float4*)(g_high_out + (size_t)(row0 + r) * 128 + lane * 4) = y;
    }
}

// ---------------- K4: projection GEMM — fp16, 512 threads (16 warps) -------
__global__ void __launch_bounds__(512) k_proj(const float* __restrict__ A,
        const float* __restrict__ wq, const float* __restrict__ wk,
        const float* __restrict__ wv, const float* __restrict__ ws) {
    extern __shared__ __half smh[];
    __half* As = smh;
    __half* Bs = smh + 128 * PAD_AH;
    int tid = threadIdx.x;
    int warp = tid >> 5;
    int wm = warp >> 1, wn = warp & 1;    // 8x2 warps; warp tile 16x32
    size_t row0 = (size_t)blockIdx.x * 128;
    int n0 = blockIdx.y * 64;
    int w = blockIdx.z;

    const float* Ws[4] = {wq, wk, wv, ws};
    float* Outs[4] = {g_q, g_k, g_v, g_skip};
    const float* B = Ws[w];

    for (int i = tid; i < 128 * 32; i += 512) {
        int r = i >> 5, ch = i & 31;
        float4 v = *(const float4*)(A + (row0 + r) * 128 + ch * 4);
        __half2* dst = (__half2*)(As + r * PAD_AH + ch * 4);
        dst[0] = __floats2half2_rn(v.x, v.y);
        dst[1] = __floats2half2_rn(v.z, v.w);
    }
    for (int i = tid; i < 128 * 16; i += 512) {
        int k = i >> 4, ch = i & 15;
        float4 v = *(const float4*)(B + k * 128 + n0 + ch * 4);
        __half2* dst = (__half2*)(Bs + k * PAD_BH + ch * 4);
        dst[0] = __floats2half2_rn(v.x, v.y);
        dst[1] = __floats2half2_rn(v.z, v.w);
    }
    __syncthreads();

    FragCH acc[2];
#pragma unroll
    for (int j = 0; j < 2; j++) wmma::fill_fragment(acc[j], 0.f);
#pragma unroll
    for (int k0 = 0; k0 < 128; k0 += 16) {
        FragAH a;
        wmma::load_matrix_sync(a, As + (wm * 16) * PAD_AH + k0, PAD_AH);
        FragBH b[2];
#pragma unroll
        for (int j = 0; j < 2; j++)
            wmma::load_matrix_sync(b[j], Bs + k0 * PAD_BH + wn * 32 + j * 16, PAD_BH);
#pragma unroll
        for (int j = 0; j < 2; j++)
            wmma::mma_sync(acc[j], a, b[j], acc[j]);
    }
    float* Out = Outs[w];
#pragma unroll
    for (int j = 0; j < 2; j++)
        wmma::store_matrix_sync(Out + (row0 + wm * 16) * 128 + n0 + wn * 32 + j * 16,
                                acc[j], 128, wmma::mem_row_major);
}

// ---------------- K5: attention — head-split (512, 2), edges via __ldg -----
__global__ void __launch_bounds__(512) k_attn(const float* __restrict__ bq,
                                              const float* __restrict__ bk,
                                              const float* __restrict__ bv) {
    extern __shared__ float sm[];
    float* qs = sm;
    float* kvs = qs + N_GENES * 33;
    float* alpha = kvs + N_GENES * 33;
    float* invd = alpha + E_GRN;
    int c = blockIdx.x, tid = threadIdx.x;
    int lane = tid & 31, warp = tid >> 5;
    int h0 = blockIdx.y * 2;
    const float* qb = g_q + (size_t)c * N_GENES * D;
    const float* kb = g_k + (size_t)c * N_GENES * D;
    const float* vb = g_v + (size_t)c * N_GENES * D;
    float* ob = g_attn + (size_t)c * N_GENES * D;
    int go0 = 0, go1 = 0;
    if (tid < N_GENES) { go0 = __ldg(g_off + tid); go1 = __ldg(g_off + tid + 1); }

    for (int h = h0; h < h0 + 2; ++h) {
        __syncthreads();
        int hb = h * HD;
        for (int i = tid; i < N_GENES * 8; i += 512) {
            int g = i >> 3, dq = (i & 7) * 4;
            float4 qv = *(const float4*)(qb + g * D + hb + dq);
            float4 kv = *(const float4*)(kb + g * D + hb + dq);
            float4 b1 = *(const float4*)(bq + hb + dq);
            float4 b2 = *(const float4*)(bk + hb + dq);
            float* qd = qs + g * 33 + dq;
            float* kd = kvs + g * 33 + dq;
            qd[0] = qv.x + b1.x; qd[1] = qv.y + b1.y; qd[2] = qv.z + b1.z; qd[3] = qv.w + b1.w;
            kd[0] = kv.x + b2.x; kd[1] = kv.y + b2.y; kd[2] = kv.z + b2.z; kd[3] = kv.w + b2.w;
        }
        __syncthreads();

        // Phase A: edge-parallel logits (edges via L1-resident g_edge)
        for (int e = tid; e < E_GRN; e += 512) {
            int pk = __ldg(g_edge + e);
            int s = pk & 0xffff, dg = pk >> 16;
            const float* qr = qs + dg * 33;
            const float* kr = kvs + s * 33;
            float t0 = 0.f, t1 = 0.f;
#pragma unroll
            for (int d = 0; d < HD; d += 2) {
                t0 = fmaf(qr[d], kr[d], t0);
                t1 = fmaf(qr[d + 1], kr[d + 1], t1);
            }
            alpha[e] = (t0 + t1) * 0.17677669529663689f;
        }
        __syncthreads();

        // Phase B: stage v+bv (k dead) + softmax (deferred normalize)
        for (int i = tid; i < N_GENES * 8; i += 512) {
            int g = i >> 3, dq = (i & 7) * 4;
            float4 vv = *(const float4*)(vb + g * D + hb + dq);
            float4 b3 = *(const float4*)(bv + hb + dq);
            float* vd = kvs + g * 33 + dq;
            vd[0] = vv.x + b3.x; vd[1] = vv.y + b3.y; vd[2] = vv.z + b3.z; vd[3] = vv.w + b3.w;
        }
        if (tid < N_GENES) {
            float inv = 0.f;
            if (go1 > go0) {
                float m = -3.4e38f;
                for (int j = go0; j < go1; ++j) m = fmaxf(m, alpha[j]);
                float den = 0.f;
                for (int j = go0; j < go1; ++j) {
                    float e = expf(alpha[j] - m);
                    alpha[j] = e;
                    den += e;
                }
                inv = 1.f / den;
            }
            invd[tid] = inv;
        }
        __syncthreads();

        // Phase C: warp-per-gene (16 warps), lane = dim; normalize at store
        for (int g = warp; g < N_GENES; g += 16) {
            int o0 = __ldg(g_off + g), o1 = __ldg(g_off + g + 1);
            float acc = 0.f;
            for (int j = o0; j < o1; ++j) {
                int s = __ldg(g_edge + j) & 0xffff;
                acc = fmaf(alpha[j], kvs[s * 33 + lane], acc);
            }
            ob[g * D + hb + lane] = acc * invd[g];
        }
    }
}

// ---------------- K6: low_out = LN(attn+skip+bskip) + gene_agg fused -------
__global__ void __launch_bounds__(512) k_lowout(const float* __restrict__ lng,
        const float* __restrict__ lnb, const float* __restrict__ bsk,
        const float* __restrict__ aw, const float* __restrict__ ab_) {
    __shared__ float part[16 * D];
    __shared__ float mvec[D];
    int c = blockIdx.x, tid = threadIdx.x;
    int lane = tid & 31, warp = tid >> 5;
    float4 gg = *(const float4*)(lng + lane * 4);
    float4 bb = *(const float4*)(lnb + lane * 4);
    float4 bs = *(const float4*)(bsk + lane * 4);
    float4 ls = make_float4(0.f, 0.f, 0.f, 0.f);
    const float* ab = g_attn + (size_t)c * N_GENES * D;
    const float* sb = g_skip + (size_t)c * N_GENES * D;
    float* lo = g_low_out + (size_t)c * N_GENES * D;
    for (int g = warp; g < N_GENES; g += 16) {
        float4 a = *(const float4*)(ab + g * D + lane * 4);
        float4 sk = *(const float4*)(sb + g * D + lane * 4);
        float4 x = make_float4(a.x + sk.x + bs.x, a.y + sk.y + bs.y,
                               a.z + sk.z + bs.z, a.w + sk.w + bs.w);
        float sum = warpSum(x.x + x.y + x.z + x.w);
        float sq = warpSum(x.x * x.x + x.y * x.y + x.z * x.z + x.w * x.w);
        float mean = sum * (1.f / D);
        float var = sq * (1.f / D) - mean * mean;
        float inv = rsqrtf(var + 1e-5f);
        float4 y;
        y.x = (x.x - mean) * inv * gg.x + bb.x;
        y.y = (x.y - mean) * inv * gg.y + bb.y;
        y.z = (x.z - mean) * inv * gg.z + bb.z;
        y.w = (x.w - mean) * inv * gg.w + bb.w;
        *(float4*)(lo + g * D + lane * 4) = y;
        ls.x += y.x; ls.y += y.y; ls.z += y.z; ls.w += y.w;
    }
    part[warp * D + lane * 4 + 0] = ls.x;
    part[warp * D + lane * 4 + 1] = ls.y;
    part[warp * D + lane * 4 + 2] = ls.z;
    part[warp * D + lane * 4 + 3] = ls.w;
    __syncthreads();
    if (tid < D) {
        float s = 0.f;
#pragma unroll
        for (int w = 0; w < 16; w++) s += part[w * D + tid];
        mvec[tid] = s * (1.f / N_GENES);
    }
    __syncthreads();
    if (tid < D) {
        float t = ab_[tid];
#pragma unroll 4
        for (int k = 0; k < D; ++k) t = fmaf(mvec[k], aw[k * D + tid], t);
        g_gene_agg[c * D + tid] = geluf(t);
    }
}

// ---------------- K8: 6 cross projections as tf32 GEMMs ----------------
__global__ void __launch_bounds__(256) k_cross6(const float* __restrict__ cw) {
    extern __shared__ float sm[];
    float* As = sm;
    float* Bs = sm + 128 * PAD_A;
    int tid = threadIdx.x;
    int warp = tid >> 5;
    int wm = warp >> 1, wn = warp & 1;
    int row0 = blockIdx.x * 128;
    int mat = blockIdx.y;
    const float* A = (mat == 1 || mat == 2 || mat == 3) ? g_gene_agg : g_high_out;
    const float* B = cw + mat * 16384;

    for (int i = tid; i < 128 * 32; i += 256) {
        int r = i >> 5, ch = i & 31;
        cp16(As + r * PAD_A + ch * 4, A + (row0 + r) * 128 + ch * 4);
        cp16(Bs + r * PAD_B + ch * 4, B + r * 128 + ch * 4);
    }
    CP_COMMIT();
    CP_WAIT0();
    __syncthreads();

    FragC acc[2][4];
#pragma unroll
    for (int i = 0; i < 2; i++)
#pragma unroll
        for (int j = 0; j < 4; j++) wmma::fill_fragment(acc[i][j], 0.f);
#pragma unroll
    for (int k0 = 0; k0 < 128; k0 += 8) {
        FragA a[2];
#pragma unroll
        for (int i = 0; i < 2; i++)
            wmma::load_matrix_sync(a[i], As + (wm * 32 + i * 16) * PAD_A + k0, PAD_A);
        FragB b[4];
#pragma unroll
        for (int j = 0; j < 4; j++)
            wmma::load_matrix_sync(b[j], Bs + k0 * PAD_B + wn * 64 + j * 16, PAD_B);
#pragma unroll
        for (int i = 0; i < 2; i++)
#pragma unroll
            for (int j = 0; j < 4; j++)
                wmma::mma_sync(acc[i][j], a[i], b[j], acc[i][j]);
    }
    float* Out = g_cross6 + mat * N_CELLS * D;
#pragma unroll
    for (int i = 0; i < 2; i++)
#pragma unroll
        for (int j = 0; j < 4; j++)
            wmma::store_matrix_sync(Out + (row0 + wm * 32 + i * 16) * 128 + wn * 64 + j * 16,
                                    acc[i][j], 128, wmma::mem_row_major);
}

// ---------------- K9: gating + high_new LN + low_cross ----------------
__global__ void k_gate(const float* __restrict__ high_emb, const float* __restrict__ cb,
                       const float* __restrict__ nhg, const float* __restrict__ nhb,
                       float* __restrict__ out_high) {
    __shared__ float red[16];
    int c = blockIdx.x, tid = threadIdx.x;
    int lane = tid & 31, warp = tid >> 5;
    const float* base = g_cross6 + c * D + tid;
    float q1 = base[0] + cb[tid];
    float k1 = base[1 * N_CELLS * D] + cb[D + tid];
    float v1 = base[2 * N_CELLS * D] + cb[2 * D + tid];
    float q2 = base[3 * N_CELLS * D] + cb[3 * D + tid];
    float k2 = base[4 * N_CELLS * D] + cb[4 * D + tid];
    float v2 = base[5 * N_CELLS * D] + cb[5 * D + tid];
    float p1 = warpSum(q1 * k1);
    float p2 = warpSum(q2 * k2);
    if (lane == 0) { red[warp] = p1; red[8 + warp] = p2; }
    __syncthreads();
    float s1 = red[0] + red[1] + red[2] + red[3];
    float s2 = red[8] + red[9] + red[10] + red[11];
    const float sc = 0.08838834764831845f;
    float g1 = sigmoidf_(s1 * sc);
    float g2 = sigmoidf_(s2 * sc);
    g_low_cross[c * D + tid] = g2 * v2;
    float x = high_emb[c * D + tid] + g_high_out[c * D + tid] + g1 * v1;
    float bs_ = warpSum(x);
    float bq_ = warpSum(x * x);
    __syncthreads();
    if (lane == 0) { red[warp] = bs_; red[8 + warp] = bq_; }
    __syncthreads();
    float sum = red[0] + red[1] + red[2] + red[3];
    float sq = red[8] + red[9] + red[10] + red[11];
    float mean = sum * (1.f / D);
    float var = sq * (1.f / D) - mean * mean;
    out_high[c * D + tid] = (x - mean) * rsqrtf(var + 1e-5f) * nhg[tid] + nhb[tid];
}

// ---------------- K10: low_new = LN(low_emb + low_out + low_cross) ----------
__global__ void k_lownew(const float* __restrict__ low_emb,
                         const float* __restrict__ nlg, const float* __restrict__ nlb,
                         float* __restrict__ out_low) {
    int tid = threadIdx.x, lane = tid & 31, warp = tid >> 5;
    int row = blockIdx.x * 8 + warp;
    int c = row >> 8;
    float4 gg = *(const float4*)(nlg + lane * 4);
    float4 bb = *(const float4*)(nlb + lane * 4);
    float4 le = *(const float4*)(low_emb + (size_t)row * D + lane * 4);
    float4 lo = *(const float4*)(g_low_out + (size_t)row * D + lane * 4);
    float4 lc = *(const float4*)(g_low_cross + c * D + lane * 4);
    float4 x = make_float4(le.x + lo.x + lc.x, le.y + lo.y + lc.y,
                           le.z + lo.z + lc.z, le.w + lo.w + lc.w);
    float sum = warpSum(x.x + x.y + x.z + x.w);
    float sq = warpSum(x.x * x.x + x.y * x.y + x.z * x.z + x.w * x.w);
    float mean = sum * (1.f / D);
    float var = sq * (1.f / D) - mean * mean;
    float inv = rsqrtf(var + 1e-5f);
    float4 y;
    y.x = (x.x - mean) * inv * gg.x + bb.x;
    y.y = (x.y - mean) * inv * gg.y + bb.y;
    y.z = (x.z - mean) * inv * gg.z + bb.z;
    y.w = (x.w - mean) * inv * gg.w + bb.w;
    *(float4*)(out_low + (size_t)row * D + lane * 4) = y;
}

// ---------------- host ----------------
extern "C" void kernel_launch(void* const* d_in, const int* in_sizes, int n_in,
                              void* d_out, int out_size) {
    const float* high = (const float*)d_in[0];
    const float* low = (const float*)d_in[1];
    const int* sp = (const int*)d_in[2];
    const int* grn = (const int*)d_in[3];
    const float* gin_w1 = (const float*)d_in[4];
    const float* gin_b1 = (const float*)d_in[5];
    const float* gin_w2 = (const float*)d_in[6];
    const float* gin_b2 = (const float*)d_in[7];
    const float* gin_eps = (const float*)d_in[8];
    const float* gin_lng = (const float*)d_in[9];
    const float* gin_lnb = (const float*)d_in[10];
    const float* wq = (const float*)d_in[11];
    const float* bq = (const float*)d_in[12];
    const float* wk = (const float*)d_in[13];
    const float* bk = (const float*)d_in[14];
    const float* wv = (const float*)d_in[15];
    const float* bv = (const float*)d_in[16];
    const float* wsk = (const float*)d_in[17];
    const float* bsk = (const float*)d_in[18];
    const float* tclng = (const float*)d_in[19];
    const float* tclnb = (const float*)d_in[20];
    const float* cw = (const float*)d_in[21];
    const float* cb = (const float*)d_in[22];
    const float* aw = (const float*)d_in[23];
    const float* ab = (const float*)d_in[24];
    const float* nhg = (const float*)d_in[25];
    const float* nhb = (const float*)d_in[26];
    const float* nlg = (const float*)d_in[27];
    const float* nlb = (const float*)d_in[28];

    float* out_high = (float*)d_out;
    float* out_low = out_high + N_CELLS * D;

    int smem_gemm1 = (128 * PAD_A + 128 * PAD_B) * (int)sizeof(float);
    int smem_proj = (128 * PAD_AH + 128 * PAD_BH) * (int)sizeof(__half);
    cudaFuncSetAttribute(k_gin1, cudaFuncAttributeMaxDynamicSharedMemorySize, smem_gemm1);
    cudaFuncSetAttribute(k_gin2, cudaFuncAttributeMaxDynamicSharedMemorySize, smem_gemm1);
    cudaFuncSetAttribute(k_proj, cudaFuncAttributeMaxDynamicSharedMemorySize, smem_proj);
    cudaFuncSetAttribute(k_cross6, cudaFuncAttributeMaxDynamicSharedMemorySize, smem_gemm1);
    int smem_attn = (2 * N_GENES * 33 + E_GRN + N_GENES) * (int)sizeof(float);
    cudaFuncSetAttribute(k_attn, cudaFuncAttributeMaxDynamicSharedMemorySize, smem_attn);

    cudaStream_t s1;
    cudaStreamCreateWithFlags(&s1, cudaStreamNonBlocking);
    cudaEvent_t evFork, evCsr, evJoin;
    cudaEventCreateWithFlags(&evFork, cudaEventDisableTiming);
    cudaEventCreateWithFlags(&evCsr, cudaEventDisableTiming);
    cudaEventCreateWithFlags(&evJoin, cudaEventDisableTiming);

    cudaEventRecord(evFork, 0);
    cudaStreamWaitEvent(s1, evFork, 0);

    // side stream: csr first (attn waits on evCsr), then high-level path
    k_csr<<<1, 256, 0, s1>>>(grn);
    cudaEventRecord(evCsr, s1);
    k_zero<<<64, 1024, 0, s1>>>();
    k_scatter<<<(E_SP * D) / 256, 256, 0, s1>>>(high, sp);
    k_gin1<<<dim3(4, 2), 256, smem_gemm1, s1>>>(high, gin_w1, gin_b1, gin_eps);
    k_gin2<<<4, 256, smem_gemm1, s1>>>(gin_w2, gin_b2, gin_lng, gin_lnb);
    cudaEventRecord(evJoin, s1);

    // main stream: proj starts immediately; attn waits for csr
    k_proj<<<dim3((N_CELLS * N_GENES) / 128, 2, 4), 512, smem_proj>>>(low, wq, wk, wv, wsk);
    cudaStreamWaitEvent(0, evCsr, 0);
    k_attn<<<dim3(N_CELLS, 2), 512, smem_attn>>>(bq, bk, bv);
    k_lowout<<<N_CELLS, 512>>>(tclng, tclnb, bsk, aw, ab);

    cudaStreamWaitEvent(0, evJoin, 0);
    k_cross6<<<dim3(4, 6), 256, smem_gemm1>>>(cw);
    k_gate<<<N_CELLS, 128>>>(high, cb, nhg, nhb, out_high);
    k_lownew<<<(N_CELLS * N_GENES) / 8, 256>>>(low, nlg, nlb, out_low);
}